// round 5
// baseline (speedup 1.0000x reference)
#include <cuda_runtime.h>
#include <cstdint>

// Problem dims
#define SEQ  512
#define BAT  64
#define INP  512
#define HID  1024
#define OUTD 512
#define BH   (64LL * 1024)   // elements per timestep slice of U / Hall (BAT*HID)

// ---------------- static device scratch (allocations are forbidden) ----------------
__device__ float g_U   [SEQ * BAT * HID];          // u_t = x_t @ Wxh^T + b_i2h
__device__ float g_Hall[(SEQ + 1) * BAT * HID];    // h_t, t = 0..512
__device__ float g_P0  [2048 * HID];               // block-local prefix (ping)
__device__ float g_P1  [2048 * HID];               // (pong)
__device__ float g_Wa  [HID * HID];                // Whh^2 / Whh^8
__device__ float g_Wb  [HID * HID];                // Whh^4 / Whh^16
__device__ float g_part[16 * BAT * HID];           // split-K partials (boundary)
__device__ float g_OUT [SEQ * BAT * OUTD];         // out_t

// ---------------- GEMM: C[r][n] = sum_k A(r,k) * B(n,k) (+bias)(+Add) ----------------
// Row addressing supports block-scatter: addr(r) = base + (r>>6)*Outer + (r&63)*Inner.
struct GP {
    const float* A; long long aO, aI; int M;       // M = real row count (clamped loads)
    const float* W; long long wn, wk;              // B(n,k) = W[n*wn + k*wk]; wk==1 -> NT
    const float* bias;                             // nullable, indexed by global n
    const float* Add; long long adO, adI;          // nullable, same row mapping as C
    float* C; long long cO, cI;
    int K, N;                                      // K is per-z when gridDim.z > 1
    float* part; long long partStride;             // split-K output: part + z*stride, ld N
};

__device__ __forceinline__ unsigned long long dup2f(float v) {
    unsigned u = __float_as_uint(v);
    unsigned long long d;
    asm("mov.b64 %0, {%1, %1};" : "=l"(d) : "r"(u));
    return d;
}
__device__ __forceinline__ void fma2(unsigned long long& d, unsigned long long a, unsigned long long b) {
    asm("fma.rn.f32x2 %0, %1, %2, %0;" : "+l"(d) : "l"(a), "l"(b));
}

__global__ __launch_bounds__(256, 1) void k_gemm(GP g) {
    __shared__ float As[2][16][128];   // [k][m]
    __shared__ float Bs[2][16][128];   // [k][n]
    const int tid = threadIdx.x;
    const int tx = tid & 15, ty = tid >> 4;          // 16 x 16 threads, 8x8 microtile
    const long long n0 = (long long)blockIdx.x * 128;
    const int mbase = blockIdx.y * 128;
    const int z = blockIdx.z;
    const bool split = (gridDim.z > 1);
    const bool wk1 = (g.wk == 1);

    const float* Abase = g.A + (split ? (long long)z * g.K : 0);   // A is k-contiguous
    const float* Wbase = g.W + (split ? (long long)z * g.K * g.wk : 0);

    // per-thread gmem assignments: 2 float4 for A, 2 float4 for B per k-tile
    const float* ap[2]; int am[2], akq[2];
    const float* bp[2]; int bi0[2], bi1[2];
    #pragma unroll
    for (int q = 0; q < 2; q++) {
        int s = tid * 2 + q;
        am[q] = s >> 2; akq[q] = s & 3;
        int mm = mbase + am[q]; if (mm > g.M - 1) mm = g.M - 1;   // clamp (M=64 case)
        ap[q] = Abase + (long long)(mm >> 6) * g.aO + (long long)(mm & 63) * g.aI + akq[q] * 4;
        if (wk1) {            // NT: k contiguous in W
            bi0[q] = s >> 2;  // n (0..127)
            bi1[q] = s & 3;   // k-quad
            bp[q] = Wbase + (n0 + bi0[q]) * g.wn + bi1[q] * 4;
        } else {              // NN: n contiguous in W
            bi0[q] = s >> 5;  // k (0..15)
            bi1[q] = s & 31;  // n-quad
            bp[q] = Wbase + (long long)bi0[q] * g.wk + n0 + bi1[q] * 4;
        }
    }

    unsigned long long acc[8][4];
    #pragma unroll
    for (int i = 0; i < 8; i++)
        #pragma unroll
        for (int j = 0; j < 4; j++) acc[i][j] = 0ull;

    const int nIter = g.K >> 4;
    float4 va[2], vb[2];

    auto loadT = [&](int k0) {
        #pragma unroll
        for (int q = 0; q < 2; q++) va[q] = *(const float4*)(ap[q] + k0);
        if (wk1) {
            #pragma unroll
            for (int q = 0; q < 2; q++) vb[q] = *(const float4*)(bp[q] + k0);
        } else {
            #pragma unroll
            for (int q = 0; q < 2; q++) vb[q] = *(const float4*)(bp[q] + (long long)k0 * g.wk);
        }
    };
    auto storeT = [&](int buf) {
        #pragma unroll
        for (int q = 0; q < 2; q++) {
            As[buf][akq[q]*4+0][am[q]] = va[q].x;
            As[buf][akq[q]*4+1][am[q]] = va[q].y;
            As[buf][akq[q]*4+2][am[q]] = va[q].z;
            As[buf][akq[q]*4+3][am[q]] = va[q].w;
            if (wk1) {
                Bs[buf][bi1[q]*4+0][bi0[q]] = vb[q].x;
                Bs[buf][bi1[q]*4+1][bi0[q]] = vb[q].y;
                Bs[buf][bi1[q]*4+2][bi0[q]] = vb[q].z;
                Bs[buf][bi1[q]*4+3][bi0[q]] = vb[q].w;
            } else {
                *(float4*)&Bs[buf][bi0[q]][bi1[q]*4] = vb[q];
            }
        }
    };

    loadT(0); storeT(0);
    __syncthreads();

    for (int it = 0; it < nIter; it++) {
        const int cur = it & 1;
        const bool pf = (it + 1 < nIter);
        if (pf) loadT((it + 1) << 4);
        #pragma unroll
        for (int k = 0; k < 16; k++) {
            float4 a0 = *(const float4*)&As[cur][k][ty*8];
            float4 a1 = *(const float4*)&As[cur][k][ty*8 + 4];
            ulonglong2 b0 = *(const ulonglong2*)&Bs[cur][k][tx*8];
            ulonglong2 b1 = *(const ulonglong2*)&Bs[cur][k][tx*8 + 4];
            unsigned long long ad[8];
            ad[0] = dup2f(a0.x); ad[1] = dup2f(a0.y); ad[2] = dup2f(a0.z); ad[3] = dup2f(a0.w);
            ad[4] = dup2f(a1.x); ad[5] = dup2f(a1.y); ad[6] = dup2f(a1.z); ad[7] = dup2f(a1.w);
            unsigned long long bv[4] = {b0.x, b0.y, b1.x, b1.y};
            #pragma unroll
            for (int i = 0; i < 8; i++)
                #pragma unroll
                for (int j = 0; j < 4; j++) fma2(acc[i][j], ad[i], bv[j]);
        }
        if (pf) storeT(cur ^ 1);
        __syncthreads();
    }

    if (split) {
        float* P = g.part + (long long)z * g.partStride;
        #pragma unroll
        for (int i = 0; i < 8; i++) {
            int r = mbase + ty*8 + i;
            if (r < g.M) {
                #pragma unroll
                for (int j = 0; j < 4; j++) {
                    float2 v;
                    v.x = __uint_as_float((unsigned)(acc[i][j]));
                    v.y = __uint_as_float((unsigned)(acc[i][j] >> 32));
                    *(float2*)(P + (long long)r * g.N + n0 + tx*8 + j*2) = v;
                }
            }
        }
    } else {
        #pragma unroll
        for (int i = 0; i < 8; i++) {
            int r = mbase + ty*8 + i;
            if (r < g.M) {
                long long ro = (long long)(r >> 6) * g.cO + (long long)(r & 63) * g.cI;
                #pragma unroll
                for (int j = 0; j < 4; j++) {
                    long long n = n0 + tx*8 + j*2;
                    float2 v;
                    v.x = __uint_as_float((unsigned)(acc[i][j]));
                    v.y = __uint_as_float((unsigned)(acc[i][j] >> 32));
                    if (g.bias) { v.x += g.bias[n]; v.y += g.bias[n + 1]; }
                    if (g.Add) {
                        const float* adp = g.Add + (long long)(r >> 6) * g.adO
                                         + (long long)(r & 63) * g.adI + n;
                        v.x += adp[0]; v.y += adp[1];
                    }
                    *(float2*)(g.C + ro + n) = v;
                }
            }
        }
    }
}

// ---------------- small helpers ----------------
// P0[g][n] = U[16*(g/64)][g%64][n]  (p_{j,1} = u_{16j})
__global__ void k_initP(float* P, const float* U) {
    long long gI = blockIdx.x; int n = threadIdx.x;
    P[gI * 1024 + n] = U[(gI >> 6) * (16 * BH) + (gI & 63) * 1024 + n];
}
__global__ void k_zero(float* p) { p[(long long)blockIdx.x * 1024 + threadIdx.x] = 0.f; }

// dst[i] = p[i] + sum_z part[z][i], i < 65536, Z = 16
__global__ void k_reduce(float* dst, const float* p, const float* part) {
    long long i = (long long)blockIdx.x * 1024 + threadIdx.x;
    float s = p[i];
    #pragma unroll
    for (int z = 0; z < 16; z++) s += part[(long long)z * BH + i];
    dst[i] = s;
}

// y = logits * mask; y -= logsumexp(y). One warp per 512-wide row.
__global__ void k_logsm(float* io, const float* mask) {
    int row  = blockIdx.x * 8 + (threadIdx.x >> 5);
    int lane = threadIdx.x & 31;
    long long base = (long long)row * OUTD + lane;
    float v[16]; float mx = -1e30f;
    #pragma unroll
    for (int i = 0; i < 16; i++) {
        v[i] = io[base + 32 * i] * mask[base + 32 * i];
        mx = fmaxf(mx, v[i]);
    }
    #pragma unroll
    for (int o = 16; o > 0; o >>= 1) mx = fmaxf(mx, __shfl_xor_sync(0xffffffffu, mx, o));
    float s = 0.f;
    #pragma unroll
    for (int i = 0; i < 16; i++) s += expf(v[i] - mx);
    #pragma unroll
    for (int o = 16; o > 0; o >>= 1) s += __shfl_xor_sync(0xffffffffu, s, o);
    float lse = mx + logf(s);
    #pragma unroll
    for (int i = 0; i < 16; i++) io[base + 32 * i] = v[i] - lse;
}

// ---------------- host orchestration ----------------
static inline void launch_g(const float* A, long long aO, long long aI, int M,
                            const float* W, long long wn, long long wk,
                            const float* bias,
                            const float* Add, long long adO, long long adI,
                            float* C, long long cO, long long cI,
                            int K, int N, int Z, float* part)
{
    GP g;
    g.A = A; g.aO = aO; g.aI = aI; g.M = M;
    g.W = W; g.wn = wn; g.wk = wk;
    g.bias = bias; g.Add = Add; g.adO = adO; g.adI = adI;
    g.C = C; g.cO = cO; g.cI = cI;
    g.K = (Z > 1) ? (K / Z) : K; g.N = N;
    g.part = part; g.partStride = BH;
    dim3 grid(N / 128, (M + 127) / 128, Z);
    k_gemm<<<grid, 256>>>(g);
}

extern "C" void kernel_launch(void* const* d_in, const int* in_sizes, int n_in,
                              void* d_out, int out_size)
{
    const float* x    = (const float*)d_in[0];   // [512,64,512]
    const float* mask = (const float*)d_in[1];   // [512,64,512]
    const float* Wi2h = (const float*)d_in[2];   // [1024,1536]
    const float* bi2h = (const float*)d_in[3];   // [1024]
    const float* Wi2o = (const float*)d_in[4];   // [512,1536]
    const float* bi2o = (const float*)d_in[5];   // [512]
    const float* Wo2o = (const float*)d_in[6];   // [512,1536]
    const float* bo2o = (const float*)d_in[7];   // [512]
    float* out = (float*)d_out;                  // [512,64,512] log-probs
    (void)in_sizes; (void)n_in; (void)out_size;

    float *U, *Hall, *P0, *P1, *Wa, *Wb, *part, *OUTb;
    cudaGetSymbolAddress((void**)&U,    g_U);
    cudaGetSymbolAddress((void**)&Hall, g_Hall);
    cudaGetSymbolAddress((void**)&P0,   g_P0);
    cudaGetSymbolAddress((void**)&P1,   g_P1);
    cudaGetSymbolAddress((void**)&Wa,   g_Wa);
    cudaGetSymbolAddress((void**)&Wb,   g_Wb);
    cudaGetSymbolAddress((void**)&part, g_part);
    cudaGetSymbolAddress((void**)&OUTb, g_OUT);

    const float* Whh = Wi2h + 512;   // [1024,1024] slice, row stride 1536

    // 1) U = X @ Wxh^T + b_i2h   (M=32768, N=1024, K=512)
    launch_g(x, 64 * 512, 512, SEQ * BAT, Wi2h, 1536, 1, bi2h,
             nullptr, 0, 0, U, BH, 1024, 512, 1024, 1, nullptr);

    // 2) W16 = Whh^16 via 4 squarings (C = A @ B, B in NN layout: wn=1)
    launch_g(Whh, 64 * 1536, 1536, 1024, Whh, 1, 1536, nullptr,
             nullptr, 0, 0, Wa, BH, 1024, 1024, 1024, 1, nullptr);           // Whh^2 -> Wa
    launch_g(Wa, BH, 1024, 1024, Wa, 1, 1024, nullptr,
             nullptr, 0, 0, Wb, BH, 1024, 1024, 1024, 1, nullptr);           // ^4 -> Wb
    launch_g(Wb, BH, 1024, 1024, Wb, 1, 1024, nullptr,
             nullptr, 0, 0, Wa, BH, 1024, 1024, 1024, 1, nullptr);           // ^8 -> Wa
    launch_g(Wa, BH, 1024, 1024, Wa, 1, 1024, nullptr,
             nullptr, 0, 0, Wb, BH, 1024, 1024, 1024, 1, nullptr);           // ^16 -> Wb

    // 3) p_{j,1} = u_{16j}
    k_initP<<<2048, 1024>>>(P0, U);

    // 4) block-local prefix finals: p_{j,i+1} = p_{j,i} @ Whh^T + u_{16j+i}, i = 1..15
    float* Pc = P0; float* Pn = P1;
    for (int i = 1; i <= 15; i++) {
        launch_g(Pc, BH, 1024, 2048, Whh, 1536, 1, nullptr,
                 U + (long long)i * BH, 16 * BH, 1024,
                 Pn, BH, 1024, 1024, 1024, 1, nullptr);
        float* t = Pc; Pc = Pn; Pn = t;
    }   // final p_{j,16} in Pc

    // 5) boundary scan: h_16 = p_0; h_{16(j+1)} = h_{16j} @ W16^T(+) + p_j  (split-K 16)
    cudaMemcpyAsync(Hall + 16 * BH, Pc, BH * sizeof(float), cudaMemcpyDeviceToDevice);
    for (int j = 1; j <= 31; j++) {
        launch_g(Hall + 16LL * j * BH, 0, 1024, 64, Wb, 1024, 1, nullptr,
                 nullptr, 0, 0, nullptr, 0, 0, 1024, 1024, 16, part);
        k_reduce<<<64, 1024>>>(Hall + 16LL * (j + 1) * BH, Pc + 64LL * j * 1024, part);
    }

    // 6) h_0 = 0
    k_zero<<<64, 1024>>>(Hall);

    // 7) refill interiors: H[16j+i+1] = H[16j+i] @ Whh^T + u_{16j+i}, i = 0..14
    //    (i = 15 rows are exactly the boundary values already in place)
    for (int i = 0; i < 15; i++) {
        launch_g(Hall + (long long)i * BH, 16 * BH, 1024, 2048, Whh, 1536, 1, nullptr,
                 U + (long long)i * BH, 16 * BH, 1024,
                 Hall + (long long)(i + 1) * BH, 16 * BH, 1024, 1024, 1024, 1, nullptr);
    }

    // 8) out_t = x_t @ Wxo^T + b_i2o + h_t @ Who^T   (two accumulating GEMMs)
    launch_g(x, 64 * 512, 512, SEQ * BAT, Wi2o, 1536, 1, bi2o,
             nullptr, 0, 0, OUTb, 64 * 512, 512, 512, 512, 1, nullptr);
    launch_g(Hall, BH, 1024, SEQ * BAT, Wi2o + 512, 1536, 1, nullptr,
             OUTb, 64 * 512, 512, OUTb, 64 * 512, 512, 1024, 512, 1, nullptr);

    // 9) oc_t = out_t @ W1^T + b_o2o + h_{t+1} @ W2^T  -> d_out
    launch_g(OUTb, 64 * 512, 512, SEQ * BAT, Wo2o, 1536, 1, bo2o,
             nullptr, 0, 0, out, 64 * 512, 512, 512, 512, 1, nullptr);
    launch_g(Hall + BH, BH, 1024, SEQ * BAT, Wo2o + 512, 1536, 1, nullptr,
             out, 64 * 512, 512, out, 64 * 512, 512, 1024, 512, 1, nullptr);

    // 10) masked log-softmax, in place on d_out
    k_logsm<<<SEQ * BAT / 8, 256>>>(out, mask);
}